// round 14
// baseline (speedup 1.0000x reference)
#include <cuda_runtime.h>

// Per-row L2 normalization: out[r,:] = in[r,:] * rsqrt(sum(in[r,:]^2))
// 16384 rows x 4096 cols fp32. 256-thread CTA per row; each thread moves the
// row with TWO 256-bit vector loads/stores (Blackwell LDG.E.256/STG.E.256).
// Combines the two empirically-winning coordinates: MLP_p1=2 (best of the
// 1/2/4/8 front-batch sweep) and 256-bit width (R12 win). 8 CTAs/SM max ->
// many independent CTA streams per SM. Streaming .cs on both paths.

#define ROWS 16384
#define THREADS 256
#define FLOATS_PER_ROW 4096
#define F_PER_OP 8                   // one 256-bit op = 8 floats
#define OPS 2                        // two ops/thread: 256 thr * 16 = 4096
#define NWARPS (THREADS / 32)        // 8

__device__ __forceinline__ void ld256_cs(const float* p, float* r) {
    asm volatile(
        "ld.global.cs.v8.f32 {%0,%1,%2,%3,%4,%5,%6,%7}, [%8];"
        : "=f"(r[0]), "=f"(r[1]), "=f"(r[2]), "=f"(r[3]),
          "=f"(r[4]), "=f"(r[5]), "=f"(r[6]), "=f"(r[7])
        : "l"(p));
}

__device__ __forceinline__ void st256_cs(float* p, const float* r) {
    asm volatile(
        "st.global.cs.v8.f32 [%0], {%1,%2,%3,%4,%5,%6,%7,%8};"
        :: "l"(p),
           "f"(r[0]), "f"(r[1]), "f"(r[2]), "f"(r[3]),
           "f"(r[4]), "f"(r[5]), "f"(r[6]), "f"(r[7])
        : "memory");
}

__global__ __launch_bounds__(THREADS)
void l2norm_row256x2_kernel(const float* __restrict__ in, float* __restrict__ out) {
    const int row = blockIdx.x;
    const int t = threadIdx.x;
    const size_t base = (size_t)row * FLOATS_PER_ROW;

    // Front-batched: two independent 256-bit streaming loads (MLP_p1 = 2).
    float v[OPS][F_PER_OP];
#pragma unroll
    for (int i = 0; i < OPS; i++) {
        ld256_cs(in + base + (size_t)(t + i * THREADS) * F_PER_OP, v[i]);
    }

    // Per-thread sum of squares over 16 values.
    float ss = 0.0f;
#pragma unroll
    for (int i = 0; i < OPS; i++)
#pragma unroll
        for (int j = 0; j < F_PER_OP; j++) ss = fmaf(v[i][j], v[i][j], ss);

    // Warp reduce.
#pragma unroll
    for (int o = 16; o > 0; o >>= 1) ss += __shfl_xor_sync(0xffffffffu, ss, o);

    // Cross-warp combine (8 warps), single barrier.
    __shared__ float warp_sum[NWARPS];
    if ((t & 31) == 0) warp_sum[t >> 5] = ss;
    __syncthreads();

    float tot = 0.0f;
#pragma unroll
    for (int w = 0; w < NWARPS; w++) tot += warp_sum[w];

    const float inv = rsqrtf(tot);

    // Scale + two 256-bit streaming stores.
#pragma unroll
    for (int i = 0; i < OPS; i++) {
        float o8[F_PER_OP];
#pragma unroll
        for (int j = 0; j < F_PER_OP; j++) o8[j] = v[i][j] * inv;
        st256_cs(out + base + (size_t)(t + i * THREADS) * F_PER_OP, o8);
    }
}

extern "C" void kernel_launch(void* const* d_in, const int* in_sizes, int n_in,
                              void* d_out, int out_size) {
    const float* in = (const float*)d_in[0];
    float* out = (float*)d_out;
    l2norm_row256x2_kernel<<<ROWS, THREADS>>>(in, out);
}

// round 15
// speedup vs baseline: 1.0248x; 1.0248x over previous
#include <cuda_runtime.h>

// Per-row L2 normalization: out[r,:] = in[r,:] * rsqrt(sum(in[r,:]^2))
// 16384 rows x 4096 cols fp32. Converged winner shape (R12): 512-thread CTA
// per row, each thread moves its slice with ONE 256-bit streaming load and
// ONE 256-bit streaming store (Blackwell LDG.E.256/STG.E.256). Single HBM
// read (registers hold the row), one barrier, 16-warp combine read as 4x
// LDS.128. 512thr/CTA empirically gives the best full-chip wall time.

#define ROWS 16384
#define THREADS 512
#define FLOATS_PER_ROW 4096
#define F_PER_THREAD 8              // 8 floats = 32 B = one 256-bit op
#define NWARPS (THREADS / 32)       // 16

__device__ __forceinline__ void ld256_cs(const float* p, float* r) {
    asm volatile(
        "ld.global.cs.v8.f32 {%0,%1,%2,%3,%4,%5,%6,%7}, [%8];"
        : "=f"(r[0]), "=f"(r[1]), "=f"(r[2]), "=f"(r[3]),
          "=f"(r[4]), "=f"(r[5]), "=f"(r[6]), "=f"(r[7])
        : "l"(p));
}

__device__ __forceinline__ void st256_cs(float* p, const float* r) {
    asm volatile(
        "st.global.cs.v8.f32 [%0], {%1,%2,%3,%4,%5,%6,%7,%8};"
        :: "l"(p),
           "f"(r[0]), "f"(r[1]), "f"(r[2]), "f"(r[3]),
           "f"(r[4]), "f"(r[5]), "f"(r[6]), "f"(r[7])
        : "memory");
}

__global__ __launch_bounds__(THREADS, 4)
void l2norm_row256b_kernel(const float* __restrict__ in, float* __restrict__ out) {
    const int t = threadIdx.x;
    const size_t off = (size_t)blockIdx.x * FLOATS_PER_ROW + (size_t)t * F_PER_THREAD;

    // One 256-bit streaming load per thread: whole row in flight per CTA.
    float v[F_PER_THREAD];
    ld256_cs(in + off, v);

    // Per-thread sum of squares over 8 values.
    float ss = 0.0f;
#pragma unroll
    for (int i = 0; i < F_PER_THREAD; i++) ss = fmaf(v[i], v[i], ss);

    // Warp reduce.
#pragma unroll
    for (int o = 16; o > 0; o >>= 1) ss += __shfl_xor_sync(0xffffffffu, ss, o);

    // Cross-warp combine (16 warps): one barrier, partials re-read as 4x LDS.128.
    __shared__ __align__(16) float warp_sum[NWARPS];
    if ((t & 31) == 0) warp_sum[t >> 5] = ss;
    __syncthreads();

    const float4* ws4 = (const float4*)warp_sum;
    float tot = 0.0f;
#pragma unroll
    for (int w = 0; w < NWARPS / 4; w++) {
        float4 p = ws4[w];
        tot += (p.x + p.y) + (p.z + p.w);
    }

    const float inv = rsqrtf(tot);

    // Scale + one 256-bit streaming store per thread.
    float o8[F_PER_THREAD];
#pragma unroll
    for (int i = 0; i < F_PER_THREAD; i++) o8[i] = v[i] * inv;
    st256_cs(out + off, o8);
}

extern "C" void kernel_launch(void* const* d_in, const int* in_sizes, int n_in,
                              void* d_out, int out_size) {
    const float* in = (const float*)d_in[0];
    float* out = (float*)d_out;
    l2norm_row256b_kernel<<<ROWS, THREADS>>>(in, out);
}